// round 13
// baseline (speedup 1.0000x reference)
#include <cuda_runtime.h>

#define TLEN   2048
#define BATCH  8192
#define CCH    2
#define CHUNK  1024
#define WARM   96
#define TILE   16
#define ROUNDS ((CHUNK + WARM) / TILE)   // 70
#define WROUND (WARM / TILE)             // 6
#define WPB    4                         // warps per block
#define BLOCKT (32 * WPB)                // 128
#define ROWSPW 16                        // rows per warp (x2 chunks = 32 vrows)
#define ROWSPB (ROWSPW * WPB)            // 64
#define NBLK   (BATCH / ROWSPB)          // 128 blocks -> 128 SMs

#define IN_VSTR    80                    // vrow stride (64B data + 16 pad): conflict-free LDS.128
#define IN_SLICE   (32 * IN_VSTR)        // 2560 B per (buf, input, warp)
#define NBUF       3
#define STG_BASE   (NBUF * 3 * WPB * IN_SLICE)  // 92160
#define STG_VSTR   144                   // staging vrow stride (128B data + 16 pad)
#define STG_WARP   (32 * STG_VSTR)       // 4608
#define SMEM_BYTES (STG_BASE + WPB * STG_WARP)  // 110592

__device__ __forceinline__ float frcp_fast(float x) {
    float r; asm("rcp.approx.f32 %0, %1;" : "=f"(r) : "f"(x)); return r;
}
__device__ __forceinline__ float ftanh_fast(float x) {
    float r; asm("tanh.approx.f32 %0, %1;" : "=f"(r) : "f"(x)); return r;
}
__device__ __forceinline__ void cpasync16(void* dst, const void* src) {
    unsigned d = (unsigned)__cvta_generic_to_shared(dst);
    asm volatile("cp.async.cg.shared.global [%0], [%1], 16;" :: "r"(d), "l"(src) : "memory");
}
__device__ __forceinline__ void stg_cs(float* p, float4 v) {
    asm volatile("st.global.cs.v4.f32 [%0], {%1,%2,%3,%4};"
                 :: "l"(p), "f"(v.x), "f"(v.y), "f"(v.z), "f"(v.w) : "memory");
}

extern __shared__ char sm[];

// 4 EKF steps; carried chain S@12 -> rcp@28 -> P'@32; outputs packed to staging
__device__ __forceinline__ void steps4(const float4 pv, const float4 hv, const float4 sv,
                                       float& p00, float& p01, float& p11,
                                       float& x0, float& x1, char* stg)
{
    const float zz[4] = {pv.x, pv.y, pv.z, pv.w};
    const float hh[4] = {hv.x, hv.y, hv.z, hv.w};
    const float ss[4] = {sv.x, sv.y, sv.z, sv.w};
    float4 o;
    #pragma unroll
    for (int j = 0; j < 4; j++) {
        const float a  = fmaf(0.25f, ftanh_fast(fmaf(5.0f, hh[j], -2.5f)), 0.75f);
        const float r  = fmaxf(100.0f * ss[j], 1.0f);
        const float q  = 0.1f * r;
        const float qs = 1.1f * r;
        const float r2 = r * r;

        const float p01n = fmaf(a, p11, p01);
        const float X    = fmaf(a, p01, p00 + qs);
        const float S    = fmaf(a, p01n, X);
        const float Sinv = frcp_fast(S);              // S >= 1

        const float rm   = p01n * r;
        const float n2   = p01n * p01n;
        const float p11n = p11 + q;
        const float xp0  = fmaf(a, x1, x0);
        const float y    = zz[j] - xp0;

        const float K0 = fmaf(-r, Sinv, 1.0f);
        const float K1 = p01n * Sinv;

        p00 = fmaf(-r2, Sinv, r);
        p01 = rm * Sinv;
        p11 = fmaf(-n2, Sinv, p11n);
        x0  = fmaf(K0, y, xp0);
        x1  = fmaf(K1, y, x1);

        if ((j & 1) == 0) { o.x = x0; o.y = x1; }
        else { o.z = x0; o.w = x1; *(float4*)(stg + (j >> 1) * 16) = o; }
    }
}

__global__ void __launch_bounds__(BLOCKT, 1)
ekf_kernel(const float* __restrict__ price,
           const float* __restrict__ hurst,
           const float* __restrict__ sigv,
           float* __restrict__ out)
{
    const int tid = threadIdx.x;
    const int w   = tid >> 5;
    const int l   = tid & 31;
    const int cc  = l & 1;                    // compute role: vrow l = (row l>>1, chunk l&1)
    const int row0w = blockIdx.x * ROWSPB + ROWSPW * w;

    // load role: lane covers rows row0w + (l>>3) + i*4 (i=0..3), 16B slot ls, chunk cl
    const size_t lrow = (size_t)(row0w + (l >> 3));
    const float* gP = price + lrow * TLEN;
    const float* gH = hurst + lrow * TLEN;
    const float* gS = sigv  + lrow * TLEN;
    const int ls = l & 3;
    const int cl = (l >> 2) & 1;              // chunk of loaded vrows (constant per lane)

    char* stgW = sm + STG_BASE + w * STG_WARP;

    // issue one round's tile for this warp (12 LDGSTS), or an empty group
    auto issue_tile = [&](int k) {
        if (k < ROUNDS) {
            const int buf = k % NBUF;
            int t0 = cl * CHUNK - WARM + TILE * k;
            if (t0 < 0) t0 = 0;               // chunk-0 warmup clamp
            #pragma unroll
            for (int inp = 0; inp < 3; inp++) {
                const float* g = (inp == 0) ? gP : (inp == 1) ? gH : gS;
                char* base = sm + ((buf * 3 + inp) * WPB + w) * IN_SLICE;
                #pragma unroll
                for (int i = 0; i < 4; i++) {
                    const int v = i * 8 + (l >> 2);   // vrow; row = i*4 + (l>>3), chunk = cl
                    cpasync16(base + v * IN_VSTR + ls * 16,
                              g + (size_t)i * 4 * TLEN + t0 + ls * 4);
                }
            }
        }
        asm volatile("cp.async.commit_group;" ::: "memory");
    };

    // prologue: two rounds in flight
    issue_tile(0);
    issue_tile(1);

    float x0 = 0.f, x1 = 0.f, p00 = 1.0f, p01 = 0.0f, p11 = 1.0f;

    #pragma unroll 1
    for (int k = 0; k < ROUNDS; k++) {
        issue_tile(k + 2);                    // pending: {k, k+1, k+2}
        asm volatile("cp.async.wait_group 2;" ::: "memory");   // tile k landed
        __syncwarp();

        const int buf = k % NBUF;
        const char* bP = sm + ((buf * 3 + 0) * WPB + w) * IN_SLICE + l * IN_VSTR;
        const char* bH = sm + ((buf * 3 + 1) * WPB + w) * IN_SLICE + l * IN_VSTR;
        const char* bS = sm + ((buf * 3 + 2) * WPB + w) * IN_SLICE + l * IN_VSTR;

        if (k == 0) {
            // init (exact for chunk 0; measurement warm-start for chunk 1)
            const float2 pz = *(const float2*)bP;
            x0 = pz.x; x1 = pz.y - pz.x;
            p00 = 1.0f; p01 = 0.0f; p11 = 1.0f;
        }
        if (k == WROUND && cc == 0) {
            // chunk 0: reset to the exact reference init at t=0
            const float2 pz = *(const float2*)bP;
            x0 = pz.x; x1 = pz.y - pz.x;
            p00 = 1.0f; p01 = 0.0f; p11 = 1.0f;
        }

        // 16 steps, outputs packed into per-warp staging
        char* stg = stgW + l * STG_VSTR;
        #pragma unroll
        for (int g4 = 0; g4 < 4; g4++) {
            const float4 pv = *(const float4*)(bP + g4 * 16);
            const float4 hv = *(const float4*)(bH + g4 * 16);
            const float4 sv = *(const float4*)(bS + g4 * 16);
            steps4(pv, hv, sv, p00, p01, p11, x0, x1, stg + g4 * 32);
        }
        __syncwarp();                          // staging visible warp-wide

        // flush: 8 streaming STG.128, each 4 aligned 128B runs
        if (k >= WROUND) {
            const int tb = TILE * (k - WROUND);   // 0..1008
            #pragma unroll
            for (int j = 0; j < 8; j++) {
                const int v   = j * 4 + (l >> 3);     // vrow
                const int row = j * 2 + (l >> 4);     // = v>>1
                const int c   = (l >> 3) & 1;         // = v&1
                const float4 val = *(const float4*)(stgW + v * STG_VSTR + (l & 7) * 16);
                float* dst = out + (size_t)(row0w + row) * (TLEN * 2)
                           + c * (CHUNK * 2) + tb * 2 + (l & 7) * 4;
                stg_cs(dst, val);              // write-once: evict-first
            }
        }
        __syncwarp();                          // staging reusable next round
    }
}

extern "C" void kernel_launch(void* const* d_in, const int* in_sizes, int n_in,
                              void* d_out, int out_size)
{
    const float* price = (const float*)d_in[0];
    const float* hurst = (const float*)d_in[1];
    const float* sigv  = (const float*)d_in[2];
    float* out = (float*)d_out;

    static bool attr_set = false;
    if (!attr_set) {
        cudaFuncSetAttribute(ekf_kernel, cudaFuncAttributeMaxDynamicSharedMemorySize, SMEM_BYTES);
        attr_set = true;
    }
    ekf_kernel<<<NBLK, BLOCKT, SMEM_BYTES>>>(price, hurst, sigv, out);
}

// round 14
// speedup vs baseline: 1.0593x; 1.0593x over previous
#include <cuda_runtime.h>

#define TLEN   2048
#define BATCH  8192
#define CCH    4
#define CHUNK  512
#define WARM   64
#define TILE   16
#define ROUNDS ((CHUNK + WARM) / TILE)   // 36
#define WROUND (WARM / TILE)             // 4
#define BLOCKT 256                       // 8 warps (proven best geometry)
#define ROWSPB 64
#define NBLK   (BATCH / ROWSPB)          // 128

#define IN_VSTR    80                    // vrow stride (64B data + 16 pad): conflict-free LDS.128
#define IN_SLICE   (32 * IN_VSTR)        // 2560 B per (buf, input, warp)
#define NBUF       3
#define STG_BASE   (NBUF * 3 * 8 * IN_SLICE)   // 184320
#define STG_VSTR   144                   // staging vrow stride (128B data + 16 pad)
#define STG_WARP   (32 * STG_VSTR)       // 4608
#define SMEM_BYTES (STG_BASE + 8 * STG_WARP)   // 221184

__device__ __forceinline__ float frcp_fast(float x) {
    float r; asm("rcp.approx.f32 %0, %1;" : "=f"(r) : "f"(x)); return r;
}
__device__ __forceinline__ float ftanh_fast(float x) {
    float r; asm("tanh.approx.f32 %0, %1;" : "=f"(r) : "f"(x)); return r;
}
__device__ __forceinline__ void cpasync16(void* dst, const void* src) {
    unsigned d = (unsigned)__cvta_generic_to_shared(dst);
    asm volatile("cp.async.cg.shared.global [%0], [%1], 16;" :: "r"(d), "l"(src) : "memory");
}
__device__ __forceinline__ void stg_cs(float* p, float4 v) {
    asm volatile("st.global.cs.v4.f32 [%0], {%1,%2,%3,%4};"
                 :: "l"(p), "f"(v.x), "f"(v.y), "f"(v.z), "f"(v.w) : "memory");
}

extern __shared__ char sm[];

// 4 EKF steps; carried chain S@12 -> rcp@28 -> P'@32; outputs packed to staging
__device__ __forceinline__ void steps4(const float4 pv, const float4 hv, const float4 sv,
                                       float& p00, float& p01, float& p11,
                                       float& x0, float& x1, char* stg)
{
    const float zz[4] = {pv.x, pv.y, pv.z, pv.w};
    const float hh[4] = {hv.x, hv.y, hv.z, hv.w};
    const float ss[4] = {sv.x, sv.y, sv.z, sv.w};
    float4 o;
    #pragma unroll
    for (int j = 0; j < 4; j++) {
        const float a  = fmaf(0.25f, ftanh_fast(fmaf(5.0f, hh[j], -2.5f)), 0.75f);
        const float r  = fmaxf(100.0f * ss[j], 1.0f);
        const float q  = 0.1f * r;
        const float qs = 1.1f * r;
        const float r2 = r * r;

        const float p01n = fmaf(a, p11, p01);
        const float X    = fmaf(a, p01, p00 + qs);
        const float S    = fmaf(a, p01n, X);
        const float Sinv = frcp_fast(S);              // S >= 1

        const float rm   = p01n * r;
        const float n2   = p01n * p01n;
        const float p11n = p11 + q;
        const float xp0  = fmaf(a, x1, x0);
        const float y    = zz[j] - xp0;

        const float K0 = fmaf(-r, Sinv, 1.0f);
        const float K1 = p01n * Sinv;

        p00 = fmaf(-r2, Sinv, r);
        p01 = rm * Sinv;
        p11 = fmaf(-n2, Sinv, p11n);
        x0  = fmaf(K0, y, xp0);
        x1  = fmaf(K1, y, x1);

        if ((j & 1) == 0) { o.x = x0; o.y = x1; }
        else { o.z = x0; o.w = x1; *(float4*)(stg + (j >> 1) * 16) = o; }
    }
}

__global__ void __launch_bounds__(BLOCKT, 1)
ekf_kernel(const float* __restrict__ price,
           const float* __restrict__ hurst,
           const float* __restrict__ sigv,
           float* __restrict__ out)
{
    const int tid = threadIdx.x;
    const int w   = tid >> 5;
    const int l   = tid & 31;
    const int cc  = l & 3;                    // this lane's chunk (compute role)
    const int row0 = blockIdx.x * ROWSPB;

    // load-role row (8 rows per warp) and 16B slot
    const size_t lrow = (size_t)(row0 + 8 * w + (l >> 2));
    const float* gP = price + lrow * TLEN;
    const float* gH = hurst + lrow * TLEN;
    const float* gS = sigv  + lrow * TLEN;
    const int ls = l & 3;

    char* stgW = sm + STG_BASE + w * STG_WARP;

    // issue one round's tile for this warp (12 LDGSTS), or an empty group
    auto issue_tile = [&](int k) {
        if (k < ROUNDS) {
            const int buf = k % NBUF;
            #pragma unroll
            for (int inp = 0; inp < 3; inp++) {
                const float* g = (inp == 0) ? gP : (inp == 1) ? gH : gS;
                char* base = sm + ((buf * 3 + inp) * 8 + w) * IN_SLICE;
                #pragma unroll
                for (int c = 0; c < 4; c++) {
                    int t0 = c * CHUNK - WARM + TILE * k;
                    if (t0 < 0) t0 = 0;       // chunk-0 warmup clamp
                    const int v = (l >> 2) * 4 + c;   // vrow index
                    cpasync16(base + v * IN_VSTR + ls * 16, g + t0 + ls * 4);
                }
            }
        }
        asm volatile("cp.async.commit_group;" ::: "memory");
    };

    // prologue: two rounds in flight
    issue_tile(0);
    issue_tile(1);

    float x0 = 0.f, x1 = 0.f, p00 = 1.0f, p01 = 0.0f, p11 = 1.0f;

    #pragma unroll 1
    for (int k = 0; k < ROUNDS; k++) {
        issue_tile(k + 2);                    // pending: {k, k+1, k+2}
        asm volatile("cp.async.wait_group 2;" ::: "memory");   // tile k landed
        __syncwarp();

        const int buf = k % NBUF;
        const char* bP = sm + ((buf * 3 + 0) * 8 + w) * IN_SLICE + l * IN_VSTR;
        const char* bH = sm + ((buf * 3 + 1) * 8 + w) * IN_SLICE + l * IN_VSTR;
        const char* bS = sm + ((buf * 3 + 2) * 8 + w) * IN_SLICE + l * IN_VSTR;

        if (k == 0) {
            // init (exact for chunk 0; measurement warm-start for chunks 1-3)
            const float2 pz = *(const float2*)bP;
            x0 = pz.x; x1 = pz.y - pz.x;
            p00 = 1.0f; p01 = 0.0f; p11 = 1.0f;
        }
        if (k == WROUND && cc == 0) {
            // chunk 0: reset to the exact reference init at t=0
            const float2 pz = *(const float2*)bP;
            x0 = pz.x; x1 = pz.y - pz.x;
            p00 = 1.0f; p01 = 0.0f; p11 = 1.0f;
        }

        // 16 steps, outputs packed into per-warp staging
        char* stg = stgW + l * STG_VSTR;
        #pragma unroll
        for (int g4 = 0; g4 < 4; g4++) {
            const float4 pv = *(const float4*)(bP + g4 * 16);
            const float4 hv = *(const float4*)(bH + g4 * 16);
            const float4 sv = *(const float4*)(bS + g4 * 16);
            steps4(pv, hv, sv, p00, p01, p11, x0, x1, stg + g4 * 32);
        }
        __syncwarp();                          // staging visible warp-wide

        // flush: 8 streaming STG.128, each 4 aligned 128B runs
        if (k >= WROUND) {
            const int tb = TILE * (k - WROUND);   // 0..496
            #pragma unroll
            for (int j = 0; j < 8; j++) {
                const int v  = j * 4 + (l >> 3);  // vrow: row j, chunk (l>>3)
                const float4 val = *(const float4*)(stgW + v * STG_VSTR + (l & 7) * 16);
                const size_t row = (size_t)(row0 + 8 * w + j);
                float* dst = out + row * (TLEN * 2) + (v & 3) * (CHUNK * 2)
                           + tb * 2 + (l & 7) * 4;
                stg_cs(dst, val);              // write-once: evict-first
            }
        }
        __syncwarp();                          // staging reusable next round
    }
}

extern "C" void kernel_launch(void* const* d_in, const int* in_sizes, int n_in,
                              void* d_out, int out_size)
{
    const float* price = (const float*)d_in[0];
    const float* hurst = (const float*)d_in[1];
    const float* sigv  = (const float*)d_in[2];
    float* out = (float*)d_out;

    static bool attr_set = false;
    if (!attr_set) {
        cudaFuncSetAttribute(ekf_kernel, cudaFuncAttributeMaxDynamicSharedMemorySize, SMEM_BYTES);
        attr_set = true;
    }
    ekf_kernel<<<NBLK, BLOCKT, SMEM_BYTES>>>(price, hurst, sigv, out);
}

// round 15
// speedup vs baseline: 1.2089x; 1.1411x over previous
#include <cuda_runtime.h>

#define TLEN   2048
#define BATCH  8192
#define CCH    4
#define CHUNK  512
#define WARM   32
#define TILE   16
#define ROUNDS ((CHUNK + WARM) / TILE)   // 34
#define WROUND (WARM / TILE)             // 2
#define BLOCKT 256                       // 8 warps (proven best geometry)
#define ROWSPB 64
#define NBLK   (BATCH / ROWSPB)          // 128

#define IN_VSTR    80                    // vrow stride (64B data + 16 pad): conflict-free LDS.128
#define IN_SLICE   (32 * IN_VSTR)        // 2560 B per (buf, input, warp)
#define NBUF       3
#define STG_BASE   (NBUF * 3 * 8 * IN_SLICE)   // 184320
#define STG_VSTR   144                   // staging vrow stride (128B data + 16 pad)
#define STG_WARP   (32 * STG_VSTR)       // 4608
#define SMEM_BYTES (STG_BASE + 8 * STG_WARP)   // 221184

__device__ __forceinline__ float frcp_fast(float x) {
    float r; asm("rcp.approx.f32 %0, %1;" : "=f"(r) : "f"(x)); return r;
}
__device__ __forceinline__ float ftanh_fast(float x) {
    float r; asm("tanh.approx.f32 %0, %1;" : "=f"(r) : "f"(x)); return r;
}
__device__ __forceinline__ void cpasync16(void* dst, const void* src) {
    unsigned d = (unsigned)__cvta_generic_to_shared(dst);
    // L2::256B prefetch: next round consumes the adjacent 64B/next line of this row
    asm volatile("cp.async.cg.shared.global.L2::256B [%0], [%1], 16;"
                 :: "r"(d), "l"(src) : "memory");
}
__device__ __forceinline__ void stg_cs(float* p, float4 v) {
    asm volatile("st.global.cs.v4.f32 [%0], {%1,%2,%3,%4};"
                 :: "l"(p), "f"(v.x), "f"(v.y), "f"(v.z), "f"(v.w) : "memory");
}

extern __shared__ char sm[];

// 4 EKF steps; carried chain S@12 -> rcp@28 -> P'@32; outputs packed to staging
__device__ __forceinline__ void steps4(const float4 pv, const float4 hv, const float4 sv,
                                       float& p00, float& p01, float& p11,
                                       float& x0, float& x1, char* stg)
{
    const float zz[4] = {pv.x, pv.y, pv.z, pv.w};
    const float hh[4] = {hv.x, hv.y, hv.z, hv.w};
    const float ss[4] = {sv.x, sv.y, sv.z, sv.w};
    float4 o;
    #pragma unroll
    for (int j = 0; j < 4; j++) {
        const float a  = fmaf(0.25f, ftanh_fast(fmaf(5.0f, hh[j], -2.5f)), 0.75f);
        const float r  = fmaxf(100.0f * ss[j], 1.0f);
        const float q  = 0.1f * r;
        const float qs = 1.1f * r;
        const float r2 = r * r;

        const float p01n = fmaf(a, p11, p01);
        const float X    = fmaf(a, p01, p00 + qs);
        const float S    = fmaf(a, p01n, X);
        const float Sinv = frcp_fast(S);              // S >= 1

        const float rm   = p01n * r;
        const float n2   = p01n * p01n;
        const float p11n = p11 + q;
        const float xp0  = fmaf(a, x1, x0);
        const float y    = zz[j] - xp0;

        const float K0 = fmaf(-r, Sinv, 1.0f);
        const float K1 = p01n * Sinv;

        p00 = fmaf(-r2, Sinv, r);
        p01 = rm * Sinv;
        p11 = fmaf(-n2, Sinv, p11n);
        x0  = fmaf(K0, y, xp0);
        x1  = fmaf(K1, y, x1);

        if ((j & 1) == 0) { o.x = x0; o.y = x1; }
        else { o.z = x0; o.w = x1; *(float4*)(stg + (j >> 1) * 16) = o; }
    }
}

__global__ void __launch_bounds__(BLOCKT, 1)
ekf_kernel(const float* __restrict__ price,
           const float* __restrict__ hurst,
           const float* __restrict__ sigv,
           float* __restrict__ out)
{
    const int tid = threadIdx.x;
    const int w   = tid >> 5;
    const int l   = tid & 31;
    const int cc  = l & 3;                    // this lane's chunk (compute role)
    const int row0 = blockIdx.x * ROWSPB;

    // load-role row (8 rows per warp) and 16B slot
    const size_t lrow = (size_t)(row0 + 8 * w + (l >> 2));
    const float* gP = price + lrow * TLEN;
    const float* gH = hurst + lrow * TLEN;
    const float* gS = sigv  + lrow * TLEN;
    const int ls = l & 3;

    char* stgW = sm + STG_BASE + w * STG_WARP;

    // issue one round's tile for this warp (12 LDGSTS), or an empty group
    auto issue_tile = [&](int k) {
        if (k < ROUNDS) {
            const int buf = k % NBUF;
            #pragma unroll
            for (int inp = 0; inp < 3; inp++) {
                const float* g = (inp == 0) ? gP : (inp == 1) ? gH : gS;
                char* base = sm + ((buf * 3 + inp) * 8 + w) * IN_SLICE;
                #pragma unroll
                for (int c = 0; c < 4; c++) {
                    int t0 = c * CHUNK - WARM + TILE * k;
                    if (t0 < 0) t0 = 0;       // chunk-0 warmup clamp
                    const int v = (l >> 2) * 4 + c;   // vrow index
                    cpasync16(base + v * IN_VSTR + ls * 16, g + t0 + ls * 4);
                }
            }
        }
        asm volatile("cp.async.commit_group;" ::: "memory");
    };

    // prologue: two rounds in flight
    issue_tile(0);
    issue_tile(1);

    float x0 = 0.f, x1 = 0.f, p00 = 1.0f, p01 = 0.0f, p11 = 1.0f;

    #pragma unroll 1
    for (int k = 0; k < ROUNDS; k++) {
        issue_tile(k + 2);                    // pending: {k, k+1, k+2}
        asm volatile("cp.async.wait_group 2;" ::: "memory");   // tile k landed
        __syncwarp();

        const int buf = k % NBUF;
        const char* bP = sm + ((buf * 3 + 0) * 8 + w) * IN_SLICE + l * IN_VSTR;
        const char* bH = sm + ((buf * 3 + 1) * 8 + w) * IN_SLICE + l * IN_VSTR;
        const char* bS = sm + ((buf * 3 + 2) * 8 + w) * IN_SLICE + l * IN_VSTR;

        if (k == 0) {
            // init (exact for chunk 0; measurement warm-start for chunks 1-3)
            const float2 pz = *(const float2*)bP;
            x0 = pz.x; x1 = pz.y - pz.x;
            p00 = 1.0f; p01 = 0.0f; p11 = 1.0f;
        }
        if (k == WROUND && cc == 0) {
            // chunk 0: reset to the exact reference init at t=0
            const float2 pz = *(const float2*)bP;
            x0 = pz.x; x1 = pz.y - pz.x;
            p00 = 1.0f; p01 = 0.0f; p11 = 1.0f;
        }

        // 16 steps, outputs packed into per-warp staging
        char* stg = stgW + l * STG_VSTR;
        #pragma unroll
        for (int g4 = 0; g4 < 4; g4++) {
            const float4 pv = *(const float4*)(bP + g4 * 16);
            const float4 hv = *(const float4*)(bH + g4 * 16);
            const float4 sv = *(const float4*)(bS + g4 * 16);
            steps4(pv, hv, sv, p00, p01, p11, x0, x1, stg + g4 * 32);
        }
        __syncwarp();                          // staging visible warp-wide

        // flush: 8 streaming STG.128, each 4 aligned 128B runs
        if (k >= WROUND) {
            const int tb = TILE * (k - WROUND);   // 0..496
            #pragma unroll
            for (int j = 0; j < 8; j++) {
                const int v  = j * 4 + (l >> 3);  // vrow: row j, chunk (l>>3)
                const float4 val = *(const float4*)(stgW + v * STG_VSTR + (l & 7) * 16);
                const size_t row = (size_t)(row0 + 8 * w + j);
                float* dst = out + row * (TLEN * 2) + (v & 3) * (CHUNK * 2)
                           + tb * 2 + (l & 7) * 4;
                stg_cs(dst, val);              // write-once: evict-first
            }
        }
        __syncwarp();                          // staging reusable next round
    }
}

extern "C" void kernel_launch(void* const* d_in, const int* in_sizes, int n_in,
                              void* d_out, int out_size)
{
    const float* price = (const float*)d_in[0];
    const float* hurst = (const float*)d_in[1];
    const float* sigv  = (const float*)d_in[2];
    float* out = (float*)d_out;

    static bool attr_set = false;
    if (!attr_set) {
        cudaFuncSetAttribute(ekf_kernel, cudaFuncAttributeMaxDynamicSharedMemorySize, SMEM_BYTES);
        attr_set = true;
    }
    ekf_kernel<<<NBLK, BLOCKT, SMEM_BYTES>>>(price, hurst, sigv, out);
}